// round 10
// baseline (speedup 1.0000x reference)
#include <cuda_runtime.h>
#include <cstdint>

// Sinkhorn: B=8, N=2048, eps=0.01, 50 fused (u,v) iterations.
//   u_i = eps*(log_mu - LSE_j((c_ij + v_j)/eps))   (old u cancels)
//   v_j = eps*(log_mu - LSE_i((c_ij + u_i)/eps))   (old v cancels)
// Base-2 domain: x = (c + w) * S, S = 1/(eps*ln2).
// R10: single fat pass per iteration reads c ONCE. Each CTA owns a 16-row
//      tile: Phase A computes u_new for its rows (warp per row); Phase B
//      re-reads the tile (L1/L2 hit) and emits per-column LSE partials
//      (max, sum) over its 16 rows. A tiny reduce kernel merges the 128
//      partials per column into v. No transpose, no ct matrix: DRAM traffic
//      per iteration drops from 268MB to ~150MB.
// All __device__ scratch referenced from device code only.
// Outputs: [pi (B*N*N), -c (B*N*N), u (B*N), v (B*N)]

#define NN 2048
#define BB 8
#define NPART 128                       // row-groups (partials) per batch
#define SINK_S  144.26950408889634f     // 1/(eps*ln2) = 100*log2(e)
#define SINK_C0 -0.07624618986159398f   // eps*log_mu = -0.01*ln(2048)
#define SINK_C1 0.006931471805599453f   // eps*ln2

__device__ float g_u[BB * NN];
__device__ float g_v[BB * NN];
// Column-LSE partials, layout [p][b][j] for coalesced reduce reads.
__device__ float g_pm[(size_t)NPART * BB * NN];
__device__ float g_ps[(size_t)NPART * BB * NN];

__device__ __forceinline__ float ex2f(float x) {
    float r; asm("ex2.approx.f32 %0, %1;" : "=f"(r) : "f"(x)); return r;
}
__device__ __forceinline__ float lg2f(float x) {
    float r; asm("lg2.approx.f32 %0, %1;" : "=f"(r) : "f"(x)); return r;
}

__global__ void __launch_bounds__(256) init_kernel() {
    int i = blockIdx.x * 256 + threadIdx.x;
    if (i < BB * NN) g_v[i] = 0.0f;
}

// ---- fat pass: u-update for 16 rows + column partials over those rows ----
// Grid: BB * NPART = 1024 CTAs, 512 threads (16 warps, warp per row).
__global__ void __launch_bounds__(512, 2) fat_pass_kernel(const float* __restrict__ c) {
    __shared__ float su[16];                     // u_new * S per tile row
    const int b  = blockIdx.x >> 7;              // batch
    const int p  = blockIdx.x & (NPART - 1);     // row-group
    const int r0 = p * 16;
    const int warp = threadIdx.x >> 5, lane = threadIdx.x & 31;
    const int row = r0 + warp;

    const float* __restrict__ crow = c + ((size_t)b * NN + row) * NN;
    const float* __restrict__ vvec = g_v + b * NN;

    // ---- Phase A: u_new for this warp's row (chunked two-phase LSE) ----
    float m = -1e30f, s = 0.0f;
    #pragma unroll
    for (int h = 0; h < 2; h++) {
        float4 xv[8];
        #pragma unroll
        for (int k = 0; k < 8; k++)
            xv[k] = reinterpret_cast<const float4*>(crow)[lane + ((h * 8 + k) << 5)];

        float m0 = -1e30f, m1 = -1e30f, m2 = -1e30f, m3 = -1e30f;
        #pragma unroll
        for (int k = 0; k < 8; k++) {
            float4 w = reinterpret_cast<const float4*>(vvec)[lane + ((h * 8 + k) << 5)];
            xv[k].x = (xv[k].x + w.x) * SINK_S;
            xv[k].y = (xv[k].y + w.y) * SINK_S;
            xv[k].z = (xv[k].z + w.z) * SINK_S;
            xv[k].w = (xv[k].w + w.w) * SINK_S;
            m0 = fmaxf(m0, xv[k].x);
            m1 = fmaxf(m1, xv[k].y);
            m2 = fmaxf(m2, xv[k].z);
            m3 = fmaxf(m3, xv[k].w);
        }
        float cm = fmaxf(fmaxf(m0, m1), fmaxf(m2, m3));

        float s0 = 0.f, s1 = 0.f, s2 = 0.f, s3 = 0.f;
        #pragma unroll
        for (int k = 0; k < 8; k++) {
            s0 += ex2f(xv[k].x - cm);
            s1 += ex2f(xv[k].y - cm);
            s2 += ex2f(xv[k].z - cm);
            s3 += ex2f(xv[k].w - cm);
        }
        float cs = (s0 + s1) + (s2 + s3);

        float mm = fmaxf(m, cm);
        s = fmaf(s, ex2f(m - mm), cs * ex2f(cm - mm));
        m = mm;
    }
    #pragma unroll
    for (int off = 16; off; off >>= 1) {
        float m2 = __shfl_xor_sync(0xffffffffu, m, off);
        float s2 = __shfl_xor_sync(0xffffffffu, s, off);
        float mm = fmaxf(m, m2);
        s = fmaf(s, ex2f(m - mm), s2 * ex2f(m2 - mm));
        m = mm;
    }
    if (lane == 0) {
        float u = fmaf(-SINK_C1, m + lg2f(s), SINK_C0);
        su[warp] = u * SINK_S;
        g_u[b * NN + row] = u;
    }
    __syncthreads();

    // ---- Phase B: column partials over the 16 tile rows ----
    // Warp w owns columns [w*128, w*128+128); lane owns 4 (float4).
    const size_t rstride = NN / 4;               // float4 per row
    const float4* __restrict__ ccol =
        reinterpret_cast<const float4*>(c + ((size_t)b * NN + r0) * NN)
        + (warp * 32 + lane);

    float4 mx = make_float4(-1e30f, -1e30f, -1e30f, -1e30f);
    #pragma unroll
    for (int r = 0; r < 16; r++) {
        float4 cc = ccol[r * rstride];           // L1/L2 hit (tile just read)
        float us = su[r];
        mx.x = fmaxf(mx.x, fmaf(cc.x, SINK_S, us));
        mx.y = fmaxf(mx.y, fmaf(cc.y, SINK_S, us));
        mx.z = fmaxf(mx.z, fmaf(cc.z, SINK_S, us));
        mx.w = fmaxf(mx.w, fmaf(cc.w, SINK_S, us));
    }
    float4 ss = make_float4(0.f, 0.f, 0.f, 0.f);
    #pragma unroll
    for (int r = 0; r < 16; r++) {
        float4 cc = ccol[r * rstride];
        float us = su[r];
        ss.x += ex2f(fmaf(cc.x, SINK_S, us) - mx.x);
        ss.y += ex2f(fmaf(cc.y, SINK_S, us) - mx.y);
        ss.z += ex2f(fmaf(cc.z, SINK_S, us) - mx.z);
        ss.w += ex2f(fmaf(cc.w, SINK_S, us) - mx.w);
    }
    const size_t pidx = ((size_t)(p * BB + b)) * NN + warp * 128 + lane * 4;
    *reinterpret_cast<float4*>(g_pm + pidx) = mx;
    *reinterpret_cast<float4*>(g_ps + pidx) = ss;
}

// ---- v-reduce: merge NPART partials per column -> v ----
// Grid: BB*NN/256 = 64 CTAs. 4 independent merge streams for ILP.
__global__ void __launch_bounds__(256) vreduce_kernel() {
    const int g = blockIdx.x * 256 + threadIdx.x;   // 0 .. BB*NN-1
    const int b = g >> 11, j = g & (NN - 1);

    float m[4] = {-1e30f, -1e30f, -1e30f, -1e30f};
    float s[4] = {0.f, 0.f, 0.f, 0.f};
    #pragma unroll 4
    for (int t = 0; t < NPART / 4; t++) {
        #pragma unroll
        for (int q = 0; q < 4; q++) {
            const int p = q * (NPART / 4) + t;
            const size_t idx = ((size_t)(p * BB + b)) * NN + j;
            float mp = g_pm[idx], sp = g_ps[idx];
            float mm = fmaxf(m[q], mp);
            s[q] = fmaf(s[q], ex2f(m[q] - mm), sp * ex2f(mp - mm));
            m[q] = mm;
        }
    }
    // merge 4 streams
    float M = fmaxf(fmaxf(m[0], m[1]), fmaxf(m[2], m[3]));
    float S = s[0] * ex2f(m[0] - M) + s[1] * ex2f(m[1] - M)
            + s[2] * ex2f(m[2] - M) + s[3] * ex2f(m[3] - M);

    float v = fmaf(-SINK_C1, M + lg2f(S), SINK_C0);
    if (v > 9e8f) v = 0.0f;                     // reference clamp
    g_v[b * NN + j] = v;
}

// ---- epilogue: pi = exp2((c+u+v)*S), -c, u, v ----
__global__ void __launch_bounds__(128) final_kernel(const float* __restrict__ c,
                                                    float* __restrict__ out) {
    const size_t BNN = (size_t)BB * NN * NN;
    const int rowid = blockIdx.x;
    const int b = rowid >> 11;
    const float u = g_u[rowid];
    const float4* __restrict__ crow =
        reinterpret_cast<const float4*>(c + (size_t)rowid * NN);
    const float4* __restrict__ vrow =
        reinterpret_cast<const float4*>(g_v + (size_t)b * NN);
    float4* pio = reinterpret_cast<float4*>(out + (size_t)rowid * NN);
    float4* nco = reinterpret_cast<float4*>(out + BNN + (size_t)rowid * NN);

    #pragma unroll 2
    for (int t = threadIdx.x; t < NN / 4; t += 128) {
        float4 cc = crow[t];
        float4 vv = vrow[t];
        float4 pi, nc;
        pi.x = ex2f(((cc.x + u) + vv.x) * SINK_S);
        pi.y = ex2f(((cc.y + u) + vv.y) * SINK_S);
        pi.z = ex2f(((cc.z + u) + vv.z) * SINK_S);
        pi.w = ex2f(((cc.w + u) + vv.w) * SINK_S);
        nc.x = -cc.x; nc.y = -cc.y; nc.z = -cc.z; nc.w = -cc.w;
        pio[t] = pi;
        nco[t] = nc;
    }
    int gid = blockIdx.x * 128 + threadIdx.x;
    if (gid < BB * NN) {
        out[2 * BNN + gid] = g_u[gid];
        out[2 * BNN + (size_t)BB * NN + gid] = g_v[gid];
    }
}

extern "C" void kernel_launch(void* const* d_in, const int* in_sizes, int n_in,
                              void* d_out, int out_size) {
    const float* c = (const float*)d_in[0];

    init_kernel<<<(BB * NN + 255) / 256, 256>>>();
    for (int it = 0; it < 50; ++it) {
        fat_pass_kernel<<<BB * NPART, 512>>>(c);   // u-update + column partials
        vreduce_kernel<<<BB * NN / 256, 256>>>();  // merge partials -> v
    }
    final_kernel<<<BB * NN, 128>>>(c, (float*)d_out);
}

// round 12
// speedup vs baseline: 1.0366x; 1.0366x over previous
#include <cuda_runtime.h>
#include <cstdint>

// Sinkhorn: B=8, N=2048, eps=0.01, 50 fused (u,v) iterations.
//   u_i = eps*(log_mu - LSE_j((c_ij + v_j)/eps))   (old u cancels)
//   v_j = eps*(log_mu - LSE_i((c_ij + u_i)/eps))   (old v cancels)
// R12 = R11 with the bias constant fixed (64, not 128):
//  one read of c per iteration. Each CTA owns a 16-row tile.
//  Phase A (warp per row): x=(c+v)S, row max m, e' = 2^(x-m+64) -> smem tile
//  AND row sum s' (same exps). u from (m, s'). r_i = 2^64/s'_i.
//  Phase B (thread per 4 cols): prod = e' * r_i = 2^(y - C0*S + 64);
//  column max P, S = sum prod/P. Partial = (lg2 P, S).
//  vreduce merges 128 partials: v_new = v_old + C1*(64 - (M + lg2 S)).
// All __device__ scratch referenced from device code only.
// Outputs: [pi (B*N*N), -c (B*N*N), u (B*N), v (B*N)]

#define NN 2048
#define BB 8
#define NPART 128                       // 16-row groups per batch
#define TPAD 2052                       // padded tile row stride (floats)
#define SINK_S  144.26950408889634f     // 1/(eps*ln2) = 100*log2(e)
#define SINK_C0 -0.07624618986159398f   // eps*log_mu = -0.01*ln(2048)
#define SINK_C1 0.006931471805599453f   // eps*ln2

__device__ float g_u[BB * NN];
__device__ float g_v[BB * NN];
// Column-LSE partials, layout [p][b][j]: pm = lg2(tile col max), ps = scaled sum.
__device__ float g_pm[(size_t)NPART * BB * NN];
__device__ float g_ps[(size_t)NPART * BB * NN];

__device__ __forceinline__ float ex2f(float x) {
    float r; asm("ex2.approx.f32 %0, %1;" : "=f"(r) : "f"(x)); return r;
}
__device__ __forceinline__ float lg2f(float x) {
    float r; asm("lg2.approx.f32 %0, %1;" : "=f"(r) : "f"(x)); return r;
}
__device__ __forceinline__ float rcpf(float x) {
    float r; asm("rcp.approx.f32 %0, %1;" : "=f"(r) : "f"(x)); return r;
}

__global__ void __launch_bounds__(256) init_kernel() {
    int i = blockIdx.x * 256 + threadIdx.x;
    if (i < BB * NN) g_v[i] = 0.0f;
}

// ---- fat pass: grid = BB*NPART = 1024 CTAs, 512 threads (16 warps) ----
__global__ void __launch_bounds__(512, 1) fat_pass_kernel(const float* __restrict__ c) {
    extern __shared__ float tile[];              // [16][TPAD] of e' values
    __shared__ float su_r[16];                   // r_i = 2^64 / s'_i per tile row
    const int b  = blockIdx.x >> 7;
    const int p  = blockIdx.x & (NPART - 1);
    const int r0 = p * 16;
    const int warp = threadIdx.x >> 5, lane = threadIdx.x & 31;
    const int row = r0 + warp;

    const float4* __restrict__ crow =
        reinterpret_cast<const float4*>(c + ((size_t)b * NN + row) * NN);
    const float4* __restrict__ vv =
        reinterpret_cast<const float4*>(g_v + b * NN);

    // ---- Phase A: row LSE, stage e' into smem ----
    float4 xv[16];
    #pragma unroll
    for (int k = 0; k < 16; k++)
        xv[k] = crow[lane + (k << 5)];           // front-batched (MLP=16)

    float m0 = -1e30f, m1 = -1e30f, m2 = -1e30f, m3 = -1e30f;
    #pragma unroll
    for (int k = 0; k < 16; k++) {
        float4 w = vv[lane + (k << 5)];          // L1-resident vector
        xv[k].x = (xv[k].x + w.x) * SINK_S;
        xv[k].y = (xv[k].y + w.y) * SINK_S;
        xv[k].z = (xv[k].z + w.z) * SINK_S;
        xv[k].w = (xv[k].w + w.w) * SINK_S;
        m0 = fmaxf(m0, xv[k].x);
        m1 = fmaxf(m1, xv[k].y);
        m2 = fmaxf(m2, xv[k].z);
        m3 = fmaxf(m3, xv[k].w);
    }
    float m = fmaxf(fmaxf(m0, m1), fmaxf(m2, m3));
    #pragma unroll
    for (int off = 16; off; off >>= 1)
        m = fmaxf(m, __shfl_xor_sync(0xffffffffu, m, off));

    float s0 = 0.f, s1 = 0.f, s2 = 0.f, s3 = 0.f;
    const float mb = m - 64.0f;                  // bias K=64
    #pragma unroll
    for (int k = 0; k < 16; k++) {
        float4 e;
        e.x = ex2f(xv[k].x - mb);
        e.y = ex2f(xv[k].y - mb);
        e.z = ex2f(xv[k].z - mb);
        e.w = ex2f(xv[k].w - mb);
        s0 += e.x; s1 += e.y; s2 += e.z; s3 += e.w;
        *reinterpret_cast<float4*>(&tile[warp * TPAD + 4 * (lane + (k << 5))]) = e;
    }
    float s = (s0 + s1) + (s2 + s3);
    #pragma unroll
    for (int off = 16; off; off >>= 1)
        s += __shfl_xor_sync(0xffffffffu, s, off);

    if (lane == 0) {
        // u = C0 - C1*(m + lg2 s_true), lg2 s_true = lg2 s' - 64
        g_u[b * NN + row] = fmaf(-SINK_C1, m + lg2f(s) - 64.0f, SINK_C0);
        su_r[warp] = rcpf(s * 0x1p-64f);         // 2^64 / s'
    }
    __syncthreads();

    // ---- Phase B: column partials over the 16 tile rows (no exps) ----
    const int j0 = threadIdx.x * 4;              // 4 columns per thread
    float4 prod[16];
    float4 pm = make_float4(1e-18f, 1e-18f, 1e-18f, 1e-18f);
    #pragma unroll
    for (int r = 0; r < 16; r++) {
        float4 e = *reinterpret_cast<const float4*>(&tile[r * TPAD + j0]);
        float rr = su_r[r];
        prod[r].x = e.x * rr;
        prod[r].y = e.y * rr;
        prod[r].z = e.z * rr;
        prod[r].w = e.w * rr;
        pm.x = fmaxf(pm.x, prod[r].x);
        pm.y = fmaxf(pm.y, prod[r].y);
        pm.z = fmaxf(pm.z, prod[r].z);
        pm.w = fmaxf(pm.w, prod[r].w);
    }
    float4 rp;
    rp.x = rcpf(pm.x); rp.y = rcpf(pm.y); rp.z = rcpf(pm.z); rp.w = rcpf(pm.w);
    float4 S4 = make_float4(0.f, 0.f, 0.f, 0.f);
    #pragma unroll
    for (int r = 0; r < 16; r++) {
        S4.x = fmaf(prod[r].x, rp.x, S4.x);
        S4.y = fmaf(prod[r].y, rp.y, S4.y);
        S4.z = fmaf(prod[r].z, rp.z, S4.z);
        S4.w = fmaf(prod[r].w, rp.w, S4.w);
    }
    float4 M4;
    M4.x = lg2f(pm.x); M4.y = lg2f(pm.y); M4.z = lg2f(pm.z); M4.w = lg2f(pm.w);

    const size_t pidx = ((size_t)(p * BB + b)) * NN + j0;
    *reinterpret_cast<float4*>(g_pm + pidx) = M4;
    *reinterpret_cast<float4*>(g_ps + pidx) = S4;
}

// ---- v-reduce: merge NPART partials per column -> v ----
__global__ void __launch_bounds__(256) vreduce_kernel() {
    const int g = blockIdx.x * 256 + threadIdx.x;   // 0 .. BB*NN-1
    const int b = g >> 11, j = g & (NN - 1);

    float m[4] = {-1e30f, -1e30f, -1e30f, -1e30f};
    float s[4] = {0.f, 0.f, 0.f, 0.f};
    #pragma unroll 4
    for (int t = 0; t < NPART / 4; t++) {
        #pragma unroll
        for (int q = 0; q < 4; q++) {
            const int p = q * (NPART / 4) + t;
            const size_t idx = ((size_t)(p * BB + b)) * NN + j;
            float mp = g_pm[idx], sp = g_ps[idx];
            float mm = fmaxf(m[q], mp);
            s[q] = fmaf(s[q], ex2f(m[q] - mm), sp * ex2f(mp - mm));
            m[q] = mm;
        }
    }
    float M = fmaxf(fmaxf(m[0], m[1]), fmaxf(m[2], m[3]));
    float S = s[0] * ex2f(m[0] - M) + s[1] * ex2f(m[1] - M)
            + s[2] * ex2f(m[2] - M) + s[3] * ex2f(m[3] - M);

    // v_new = v_old + C1 * (K - (M + lg2 S)), K = 64 (single net bias)
    float v = g_v[g] + SINK_C1 * (64.0f - (M + lg2f(S)));
    if (v > 9e8f) v = 0.0f;                     // reference clamp
    g_v[g] = v;
}

// ---- epilogue: pi = exp2((c+u+v)*S), -c, u, v ----
__global__ void __launch_bounds__(128) final_kernel(const float* __restrict__ c,
                                                    float* __restrict__ out) {
    const size_t BNN = (size_t)BB * NN * NN;
    const int rowid = blockIdx.x;
    const int b = rowid >> 11;
    const float u = g_u[rowid];
    const float4* __restrict__ crow =
        reinterpret_cast<const float4*>(c + (size_t)rowid * NN);
    const float4* __restrict__ vrow =
        reinterpret_cast<const float4*>(g_v + (size_t)b * NN);
    float4* pio = reinterpret_cast<float4*>(out + (size_t)rowid * NN);
    float4* nco = reinterpret_cast<float4*>(out + BNN + (size_t)rowid * NN);

    #pragma unroll 2
    for (int t = threadIdx.x; t < NN / 4; t += 128) {
        float4 cc = crow[t];
        float4 vv = vrow[t];
        float4 pi, nc;
        pi.x = ex2f(((cc.x + u) + vv.x) * SINK_S);
        pi.y = ex2f(((cc.y + u) + vv.y) * SINK_S);
        pi.z = ex2f(((cc.z + u) + vv.z) * SINK_S);
        pi.w = ex2f(((cc.w + u) + vv.w) * SINK_S);
        nc.x = -cc.x; nc.y = -cc.y; nc.z = -cc.z; nc.w = -cc.w;
        pio[t] = pi;
        nco[t] = nc;
    }
    int gid = blockIdx.x * 128 + threadIdx.x;
    if (gid < BB * NN) {
        out[2 * BNN + gid] = g_u[gid];
        out[2 * BNN + (size_t)BB * NN + gid] = g_v[gid];
    }
}

extern "C" void kernel_launch(void* const* d_in, const int* in_sizes, int n_in,
                              void* d_out, int out_size) {
    const float* c = (const float*)d_in[0];
    const int SMEM = 16 * TPAD * 4;             // 131,328 bytes

    cudaFuncSetAttribute(fat_pass_kernel,
                         cudaFuncAttributeMaxDynamicSharedMemorySize, SMEM);

    init_kernel<<<(BB * NN + 255) / 256, 256>>>();
    for (int it = 0; it < 50; ++it) {
        fat_pass_kernel<<<BB * NPART, 512, SMEM>>>(c);   // u + column partials
        vreduce_kernel<<<BB * NN / 256, 256>>>();        // partials -> v
    }
    final_kernel<<<BB * NN, 128>>>(c, (float*)d_out);
}

// round 13
// speedup vs baseline: 1.3279x; 1.2810x over previous
#include <cuda_runtime.h>
#include <cstdint>

// Sinkhorn: B=8, N=2048, eps=0.01, 50 fused (u,v) iterations.
//   u_i = eps*(log_mu - LSE_j((c_ij + v_j)/eps))   (old u cancels)
//   v_j = eps*(log_mu - LSE_i((c_ij + u_i)/eps))   (old v cancels)
// R13: one read of c per iteration; 8-row tiles (2 CTAs/SM) and a
//  latency-parallel v-reduce.
//  Fat pass (256 thr, warp per row): Phase A computes x=(c+v)S, row max m,
//  e' = 2^(x-m+64) -> smem AND row sum s' (same exps); u from (m, s');
//  r_i = 2^64/s'_i. Phase B (thread per 4 cols, 2 groups): prod = e'*r_i
//  = 2^(y - C0*S + 64); column max P, S = sum prod/P; partial = (lg2 P, S).
//  vreduce (512 CTAs): 8-way p-split per column, smem combine:
//  v_new = v_old + C1*(64 - (M + lg2 S)).
// All __device__ scratch referenced from device code only.
// Outputs: [pi (B*N*N), -c (B*N*N), u (B*N), v (B*N)]

#define NN 2048
#define BB 8
#define TROWS 8                         // tile rows per CTA
#define NPART 256                       // row-groups (= NN/TROWS) per batch
#define TPAD 2052                       // padded tile row stride (floats)
#define SINK_S  144.26950408889634f     // 1/(eps*ln2) = 100*log2(e)
#define SINK_C0 -0.07624618986159398f   // eps*log_mu = -0.01*ln(2048)
#define SINK_C1 0.006931471805599453f   // eps*ln2

__device__ float g_u[BB * NN];
__device__ float g_v[BB * NN];
// Column-LSE partials, layout [p][b][j]: pm = lg2(tile col max), ps = scaled sum.
__device__ float g_pm[(size_t)NPART * BB * NN];
__device__ float g_ps[(size_t)NPART * BB * NN];

__device__ __forceinline__ float ex2f(float x) {
    float r; asm("ex2.approx.f32 %0, %1;" : "=f"(r) : "f"(x)); return r;
}
__device__ __forceinline__ float lg2f(float x) {
    float r; asm("lg2.approx.f32 %0, %1;" : "=f"(r) : "f"(x)); return r;
}
__device__ __forceinline__ float rcpf(float x) {
    float r; asm("rcp.approx.f32 %0, %1;" : "=f"(r) : "f"(x)); return r;
}

__global__ void __launch_bounds__(256) init_kernel() {
    int i = blockIdx.x * 256 + threadIdx.x;
    if (i < BB * NN) g_v[i] = 0.0f;
}

// ---- fat pass: grid = BB*NPART = 2048 CTAs, 256 threads (8 warps) ----
__global__ void __launch_bounds__(256, 2) fat_pass_kernel(const float* __restrict__ c) {
    extern __shared__ float tile[];              // [TROWS][TPAD] of e' values
    __shared__ float su_r[TROWS];                // r_i = 2^64 / s'_i per tile row
    const int b  = blockIdx.x >> 8;              // / NPART
    const int p  = blockIdx.x & (NPART - 1);
    const int r0 = p * TROWS;
    const int warp = threadIdx.x >> 5, lane = threadIdx.x & 31;
    const int row = r0 + warp;

    const float4* __restrict__ crow =
        reinterpret_cast<const float4*>(c + ((size_t)b * NN + row) * NN);
    const float4* __restrict__ vv =
        reinterpret_cast<const float4*>(g_v + b * NN);

    // ---- Phase A: row LSE, stage e' into smem ----
    float4 xv[16];
    #pragma unroll
    for (int k = 0; k < 16; k++)
        xv[k] = crow[lane + (k << 5)];           // front-batched (MLP=16)

    float m0 = -1e30f, m1 = -1e30f, m2 = -1e30f, m3 = -1e30f;
    #pragma unroll
    for (int k = 0; k < 16; k++) {
        float4 w = vv[lane + (k << 5)];          // L1-resident vector
        xv[k].x = (xv[k].x + w.x) * SINK_S;
        xv[k].y = (xv[k].y + w.y) * SINK_S;
        xv[k].z = (xv[k].z + w.z) * SINK_S;
        xv[k].w = (xv[k].w + w.w) * SINK_S;
        m0 = fmaxf(m0, xv[k].x);
        m1 = fmaxf(m1, xv[k].y);
        m2 = fmaxf(m2, xv[k].z);
        m3 = fmaxf(m3, xv[k].w);
    }
    float m = fmaxf(fmaxf(m0, m1), fmaxf(m2, m3));
    #pragma unroll
    for (int off = 16; off; off >>= 1)
        m = fmaxf(m, __shfl_xor_sync(0xffffffffu, m, off));

    float s0 = 0.f, s1 = 0.f, s2 = 0.f, s3 = 0.f;
    const float mb = m - 64.0f;                  // bias K=64
    #pragma unroll
    for (int k = 0; k < 16; k++) {
        float4 e;
        e.x = ex2f(xv[k].x - mb);
        e.y = ex2f(xv[k].y - mb);
        e.z = ex2f(xv[k].z - mb);
        e.w = ex2f(xv[k].w - mb);
        s0 += e.x; s1 += e.y; s2 += e.z; s3 += e.w;
        *reinterpret_cast<float4*>(&tile[warp * TPAD + 4 * (lane + (k << 5))]) = e;
    }
    float s = (s0 + s1) + (s2 + s3);
    #pragma unroll
    for (int off = 16; off; off >>= 1)
        s += __shfl_xor_sync(0xffffffffu, s, off);

    if (lane == 0) {
        // u = C0 - C1*(m + lg2 s_true), lg2 s_true = lg2 s' - 64
        g_u[b * NN + row] = fmaf(-SINK_C1, m + lg2f(s) - 64.0f, SINK_C0);
        su_r[warp] = rcpf(s * 0x1p-64f);         // 2^64 / s'
    }
    __syncthreads();

    // ---- Phase B: column partials over the TROWS tile rows (no exps) ----
    #pragma unroll
    for (int g2 = 0; g2 < 2; g2++) {
        const int j0 = (threadIdx.x + (g2 << 8)) << 2;   // 4 columns per thread
        float4 prod[TROWS];
        float4 pm = make_float4(1e-18f, 1e-18f, 1e-18f, 1e-18f);
        #pragma unroll
        for (int r = 0; r < TROWS; r++) {
            float4 e = *reinterpret_cast<const float4*>(&tile[r * TPAD + j0]);
            float rr = su_r[r];
            prod[r].x = e.x * rr;
            prod[r].y = e.y * rr;
            prod[r].z = e.z * rr;
            prod[r].w = e.w * rr;
            pm.x = fmaxf(pm.x, prod[r].x);
            pm.y = fmaxf(pm.y, prod[r].y);
            pm.z = fmaxf(pm.z, prod[r].z);
            pm.w = fmaxf(pm.w, prod[r].w);
        }
        float4 rp;
        rp.x = rcpf(pm.x); rp.y = rcpf(pm.y); rp.z = rcpf(pm.z); rp.w = rcpf(pm.w);
        float4 S4 = make_float4(0.f, 0.f, 0.f, 0.f);
        #pragma unroll
        for (int r = 0; r < TROWS; r++) {
            S4.x = fmaf(prod[r].x, rp.x, S4.x);
            S4.y = fmaf(prod[r].y, rp.y, S4.y);
            S4.z = fmaf(prod[r].z, rp.z, S4.z);
            S4.w = fmaf(prod[r].w, rp.w, S4.w);
        }
        float4 M4;
        M4.x = lg2f(pm.x); M4.y = lg2f(pm.y); M4.z = lg2f(pm.z); M4.w = lg2f(pm.w);

        const size_t pidx = ((size_t)(p * BB + b)) * NN + j0;
        *reinterpret_cast<float4*>(g_pm + pidx) = M4;
        *reinterpret_cast<float4*>(g_ps + pidx) = S4;
    }
}

// ---- v-reduce: merge NPART partials per column -> v ----
// Grid = BB*NN/32 = 512 CTAs; 8 warps; warp pg handles p in [pg*32, pg*32+32)
// for 32 consecutive columns (lane = column). Coalesced 128B lines.
__global__ void __launch_bounds__(256) vreduce_kernel() {
    __shared__ float sm_m[8][32], sm_s[8][32];
    const int tx = threadIdx.x & 31, pg = threadIdx.x >> 5;
    const int G = blockIdx.x * 32 + tx;            // global column id
    const int b = G >> 11, j = G & (NN - 1);

    float m[4] = {-1e30f, -1e30f, -1e30f, -1e30f};
    float s[4] = {0.f, 0.f, 0.f, 0.f};
    #pragma unroll
    for (int t = 0; t < 8; t++) {
        #pragma unroll
        for (int q = 0; q < 4; q++) {
            const int p = pg * 32 + q * 8 + t;
            const size_t idx = ((size_t)(p * BB + b)) * NN + j;
            float mp = g_pm[idx], sp = g_ps[idx];
            float mm = fmaxf(m[q], mp);
            s[q] = fmaf(s[q], ex2f(m[q] - mm), sp * ex2f(mp - mm));
            m[q] = mm;
        }
    }
    float M = fmaxf(fmaxf(m[0], m[1]), fmaxf(m[2], m[3]));
    float S = s[0] * ex2f(m[0] - M) + s[1] * ex2f(m[1] - M)
            + s[2] * ex2f(m[2] - M) + s[3] * ex2f(m[3] - M);
    sm_m[pg][tx] = M;
    sm_s[pg][tx] = S;
    __syncthreads();

    if (threadIdx.x < 32) {
        float Mf = sm_m[0][tx], Sf = sm_s[0][tx];
        #pragma unroll
        for (int k = 1; k < 8; k++) {
            float mp = sm_m[k][tx], sp = sm_s[k][tx];
            float mm = fmaxf(Mf, mp);
            Sf = fmaf(Sf, ex2f(Mf - mm), sp * ex2f(mp - mm));
            Mf = mm;
        }
        // v_new = v_old + C1 * (K - (M + lg2 S)), K = 64 (single net bias)
        const int gcol = blockIdx.x * 32 + tx;
        float v = g_v[gcol] + SINK_C1 * (64.0f - (Mf + lg2f(Sf)));
        if (v > 9e8f) v = 0.0f;                    // reference clamp
        g_v[gcol] = v;
    }
}

// ---- epilogue: pi = exp2((c+u+v)*S), -c, u, v ----
__global__ void __launch_bounds__(128) final_kernel(const float* __restrict__ c,
                                                    float* __restrict__ out) {
    const size_t BNN = (size_t)BB * NN * NN;
    const int rowid = blockIdx.x;
    const int b = rowid >> 11;
    const float u = g_u[rowid];
    const float4* __restrict__ crow =
        reinterpret_cast<const float4*>(c + (size_t)rowid * NN);
    const float4* __restrict__ vrow =
        reinterpret_cast<const float4*>(g_v + (size_t)b * NN);
    float4* pio = reinterpret_cast<float4*>(out + (size_t)rowid * NN);
    float4* nco = reinterpret_cast<float4*>(out + BNN + (size_t)rowid * NN);

    #pragma unroll 2
    for (int t = threadIdx.x; t < NN / 4; t += 128) {
        float4 cc = crow[t];
        float4 vv = vrow[t];
        float4 pi, nc;
        pi.x = ex2f(((cc.x + u) + vv.x) * SINK_S);
        pi.y = ex2f(((cc.y + u) + vv.y) * SINK_S);
        pi.z = ex2f(((cc.z + u) + vv.z) * SINK_S);
        pi.w = ex2f(((cc.w + u) + vv.w) * SINK_S);
        nc.x = -cc.x; nc.y = -cc.y; nc.z = -cc.z; nc.w = -cc.w;
        pio[t] = pi;
        nco[t] = nc;
    }
    int gid = blockIdx.x * 128 + threadIdx.x;
    if (gid < BB * NN) {
        out[2 * BNN + gid] = g_u[gid];
        out[2 * BNN + (size_t)BB * NN + gid] = g_v[gid];
    }
}

extern "C" void kernel_launch(void* const* d_in, const int* in_sizes, int n_in,
                              void* d_out, int out_size) {
    const float* c = (const float*)d_in[0];
    const int SMEM = TROWS * TPAD * 4;          // 65,664 bytes -> 2 CTAs/SM

    cudaFuncSetAttribute(fat_pass_kernel,
                         cudaFuncAttributeMaxDynamicSharedMemorySize, SMEM);

    init_kernel<<<(BB * NN + 255) / 256, 256>>>();
    for (int it = 0; it < 50; ++it) {
        fat_pass_kernel<<<BB * NPART, 256, SMEM>>>(c);   // u + column partials
        vreduce_kernel<<<BB * NN / 32, 256>>>();         // partials -> v
    }
    final_kernel<<<BB * NN, 128>>>(c, (float*)d_out);
}

// round 14
// speedup vs baseline: 1.3476x; 1.0149x over previous
#include <cuda_runtime.h>
#include <cstdint>

// Sinkhorn: B=8, N=2048, eps=0.01, 50 fused (u,v) iterations.
//   u_i = eps*(log_mu - LSE_j((c_ij + v_j)/eps))   (old u cancels)
//   v_j = eps*(log_mu - LSE_i((c_ij + u_i)/eps))   (old v cancels)
// R14: one read of c per iteration; 8-row tiles; Phase A processes the row
//  in 2 chunks with CHUNK-LOCAL maxes (e'_h = 2^(x-m_h+64) stored right
//  away -> only 8 float4 live regs), and Phase B uses per-(row,chunk)
//  scales su_r[r][h] = 2^(m_h-m) * 2^64/s' so prod = 2^(x-m+64)*2^64/s'
//  exactly as R13. Regs ~70 -> 3 CTAs/SM (launch_bounds(256,3)).
//  vreduce merges 256 partials: v_new = v_old + C1*(64 - (M + lg2 S)).
// All __device__ scratch referenced from device code only.
// Outputs: [pi (B*N*N), -c (B*N*N), u (B*N), v (B*N)]

#define NN 2048
#define BB 8
#define TROWS 8                         // tile rows per CTA
#define NPART 256                       // row-groups (= NN/TROWS) per batch
#define TPAD 2052                       // padded tile row stride (floats)
#define SINK_S  144.26950408889634f     // 1/(eps*ln2) = 100*log2(e)
#define SINK_C0 -0.07624618986159398f   // eps*log_mu = -0.01*ln(2048)
#define SINK_C1 0.006931471805599453f   // eps*ln2

__device__ float g_u[BB * NN];
__device__ float g_v[BB * NN];
// Column-LSE partials, layout [p][b][j]: pm = lg2(tile col max), ps = scaled sum.
__device__ float g_pm[(size_t)NPART * BB * NN];
__device__ float g_ps[(size_t)NPART * BB * NN];

__device__ __forceinline__ float ex2f(float x) {
    float r; asm("ex2.approx.f32 %0, %1;" : "=f"(r) : "f"(x)); return r;
}
__device__ __forceinline__ float lg2f(float x) {
    float r; asm("lg2.approx.f32 %0, %1;" : "=f"(r) : "f"(x)); return r;
}
__device__ __forceinline__ float rcpf(float x) {
    float r; asm("rcp.approx.f32 %0, %1;" : "=f"(r) : "f"(x)); return r;
}

__global__ void __launch_bounds__(256) init_kernel() {
    int i = blockIdx.x * 256 + threadIdx.x;
    if (i < BB * NN) g_v[i] = 0.0f;
}

// ---- fat pass: grid = BB*NPART = 2048 CTAs, 256 threads (8 warps) ----
__global__ void __launch_bounds__(256, 3) fat_pass_kernel(const float* __restrict__ c) {
    extern __shared__ float tile[];              // [TROWS][TPAD] of e' values
    __shared__ float su_r[TROWS][2];             // per-(row,chunk) Phase-B scale
    const int b  = blockIdx.x >> 8;              // / NPART
    const int p  = blockIdx.x & (NPART - 1);
    const int r0 = p * TROWS;
    const int warp = threadIdx.x >> 5, lane = threadIdx.x & 31;
    const int row = r0 + warp;

    const float4* __restrict__ crow =
        reinterpret_cast<const float4*>(c + ((size_t)b * NN + row) * NN);
    const float4* __restrict__ vv =
        reinterpret_cast<const float4*>(g_v + b * NN);

    // ---- Phase A: chunked row LSE with chunk-local maxes ----
    float mh[2], sh[2];
    #pragma unroll
    for (int h = 0; h < 2; h++) {
        float4 xv[8];
        #pragma unroll
        for (int k = 0; k < 8; k++)
            xv[k] = crow[lane + ((h * 8 + k) << 5)];   // front-batched (MLP=8)

        float m0 = -1e30f, m1 = -1e30f, m2 = -1e30f, m3 = -1e30f;
        #pragma unroll
        for (int k = 0; k < 8; k++) {
            float4 w = vv[lane + ((h * 8 + k) << 5)];  // L1-resident vector
            xv[k].x = (xv[k].x + w.x) * SINK_S;
            xv[k].y = (xv[k].y + w.y) * SINK_S;
            xv[k].z = (xv[k].z + w.z) * SINK_S;
            xv[k].w = (xv[k].w + w.w) * SINK_S;
            m0 = fmaxf(m0, xv[k].x);
            m1 = fmaxf(m1, xv[k].y);
            m2 = fmaxf(m2, xv[k].z);
            m3 = fmaxf(m3, xv[k].w);
        }
        float m = fmaxf(fmaxf(m0, m1), fmaxf(m2, m3));
        #pragma unroll
        for (int off = 16; off; off >>= 1)
            m = fmaxf(m, __shfl_xor_sync(0xffffffffu, m, off));

        const float mb = m - 64.0f;                    // chunk bias
        float s0 = 0.f, s1 = 0.f, s2 = 0.f, s3 = 0.f;
        #pragma unroll
        for (int k = 0; k < 8; k++) {
            float4 e;
            e.x = ex2f(xv[k].x - mb);
            e.y = ex2f(xv[k].y - mb);
            e.z = ex2f(xv[k].z - mb);
            e.w = ex2f(xv[k].w - mb);
            s0 += e.x; s1 += e.y; s2 += e.z; s3 += e.w;
            *reinterpret_cast<float4*>(
                &tile[warp * TPAD + 4 * (lane + ((h * 8 + k) << 5))]) = e;
        }
        float s = (s0 + s1) + (s2 + s3);
        #pragma unroll
        for (int off = 16; off; off >>= 1)
            s += __shfl_xor_sync(0xffffffffu, s, off);
        mh[h] = m;
        sh[h] = s;
    }

    if (lane == 0) {
        // Combine chunks: s' = s1*2^(m1-m) + s2*2^(m2-m)  (2^64-biased units)
        float m = fmaxf(mh[0], mh[1]);
        float e0 = ex2f(mh[0] - m), e1 = ex2f(mh[1] - m);
        float s = fmaf(sh[0], e0, sh[1] * e1);
        // u = C0 - C1*(m + lg2 s_true), lg2 s_true = lg2 s - 64
        g_u[b * NN + row] = fmaf(-SINK_C1, m + lg2f(s) - 64.0f, SINK_C0);
        float rr = rcpf(s * 0x1p-64f);             // 2^64 / s'
        su_r[warp][0] = rr * e0;                   // scale for chunk 0
        su_r[warp][1] = rr * e1;                   // scale for chunk 1
    }
    __syncthreads();

    // ---- Phase B: column partials over the TROWS tile rows (no exps) ----
    #pragma unroll
    for (int g2 = 0; g2 < 2; g2++) {
        const int j0 = (threadIdx.x + (g2 << 8)) << 2;   // 4 cols, chunk = g2
        float4 prod[TROWS];
        float4 pm = make_float4(1e-18f, 1e-18f, 1e-18f, 1e-18f);
        #pragma unroll
        for (int r = 0; r < TROWS; r++) {
            float4 e = *reinterpret_cast<const float4*>(&tile[r * TPAD + j0]);
            float rr = su_r[r][g2];
            prod[r].x = e.x * rr;
            prod[r].y = e.y * rr;
            prod[r].z = e.z * rr;
            prod[r].w = e.w * rr;
            pm.x = fmaxf(pm.x, prod[r].x);
            pm.y = fmaxf(pm.y, prod[r].y);
            pm.z = fmaxf(pm.z, prod[r].z);
            pm.w = fmaxf(pm.w, prod[r].w);
        }
        float4 rp;
        rp.x = rcpf(pm.x); rp.y = rcpf(pm.y); rp.z = rcpf(pm.z); rp.w = rcpf(pm.w);
        float4 S4 = make_float4(0.f, 0.f, 0.f, 0.f);
        #pragma unroll
        for (int r = 0; r < TROWS; r++) {
            S4.x = fmaf(prod[r].x, rp.x, S4.x);
            S4.y = fmaf(prod[r].y, rp.y, S4.y);
            S4.z = fmaf(prod[r].z, rp.z, S4.z);
            S4.w = fmaf(prod[r].w, rp.w, S4.w);
        }
        float4 M4;
        M4.x = lg2f(pm.x); M4.y = lg2f(pm.y); M4.z = lg2f(pm.z); M4.w = lg2f(pm.w);

        const size_t pidx = ((size_t)(p * BB + b)) * NN + j0;
        *reinterpret_cast<float4*>(g_pm + pidx) = M4;
        *reinterpret_cast<float4*>(g_ps + pidx) = S4;
    }
}

// ---- v-reduce: merge NPART partials per column -> v ----
// Grid = BB*NN/32 = 512 CTAs; 8 warps; warp pg handles p in [pg*32, pg*32+32)
// for 32 consecutive columns (lane = column). Coalesced 128B lines.
__global__ void __launch_bounds__(256) vreduce_kernel() {
    __shared__ float sm_m[8][32], sm_s[8][32];
    const int tx = threadIdx.x & 31, pg = threadIdx.x >> 5;
    const int G = blockIdx.x * 32 + tx;            // global column id
    const int b = G >> 11, j = G & (NN - 1);

    float m[4] = {-1e30f, -1e30f, -1e30f, -1e30f};
    float s[4] = {0.f, 0.f, 0.f, 0.f};
    #pragma unroll
    for (int t = 0; t < 8; t++) {
        #pragma unroll
        for (int q = 0; q < 4; q++) {
            const int p = pg * 32 + q * 8 + t;
            const size_t idx = ((size_t)(p * BB + b)) * NN + j;
            float mp = g_pm[idx], sp = g_ps[idx];
            float mm = fmaxf(m[q], mp);
            s[q] = fmaf(s[q], ex2f(m[q] - mm), sp * ex2f(mp - mm));
            m[q] = mm;
        }
    }
    float M = fmaxf(fmaxf(m[0], m[1]), fmaxf(m[2], m[3]));
    float S = s[0] * ex2f(m[0] - M) + s[1] * ex2f(m[1] - M)
            + s[2] * ex2f(m[2] - M) + s[3] * ex2f(m[3] - M);
    sm_m[pg][tx] = M;
    sm_s[pg][tx] = S;
    __syncthreads();

    if (threadIdx.x < 32) {
        float Mf = sm_m[0][tx], Sf = sm_s[0][tx];
        #pragma unroll
        for (int k = 1; k < 8; k++) {
            float mp = sm_m[k][tx], sp = sm_s[k][tx];
            float mm = fmaxf(Mf, mp);
            Sf = fmaf(Sf, ex2f(Mf - mm), sp * ex2f(mp - mm));
            Mf = mm;
        }
        // v_new = v_old + C1 * (K - (M + lg2 S)), K = 64 (single net bias)
        const int gcol = blockIdx.x * 32 + tx;
        float v = g_v[gcol] + SINK_C1 * (64.0f - (Mf + lg2f(Sf)));
        if (v > 9e8f) v = 0.0f;                    // reference clamp
        g_v[gcol] = v;
    }
}

// ---- epilogue: pi = exp2((c+u+v)*S), -c, u, v ----
__global__ void __launch_bounds__(128) final_kernel(const float* __restrict__ c,
                                                    float* __restrict__ out) {
    const size_t BNN = (size_t)BB * NN * NN;
    const int rowid = blockIdx.x;
    const int b = rowid >> 11;
    const float u = g_u[rowid];
    const float4* __restrict__ crow =
        reinterpret_cast<const float4*>(c + (size_t)rowid * NN);
    const float4* __restrict__ vrow =
        reinterpret_cast<const float4*>(g_v + (size_t)b * NN);
    float4* pio = reinterpret_cast<float4*>(out + (size_t)rowid * NN);
    float4* nco = reinterpret_cast<float4*>(out + BNN + (size_t)rowid * NN);

    #pragma unroll 2
    for (int t = threadIdx.x; t < NN / 4; t += 128) {
        float4 cc = crow[t];
        float4 vv = vrow[t];
        float4 pi, nc;
        pi.x = ex2f(((cc.x + u) + vv.x) * SINK_S);
        pi.y = ex2f(((cc.y + u) + vv.y) * SINK_S);
        pi.z = ex2f(((cc.z + u) + vv.z) * SINK_S);
        pi.w = ex2f(((cc.w + u) + vv.w) * SINK_S);
        nc.x = -cc.x; nc.y = -cc.y; nc.z = -cc.z; nc.w = -cc.w;
        pio[t] = pi;
        nco[t] = nc;
    }
    int gid = blockIdx.x * 128 + threadIdx.x;
    if (gid < BB * NN) {
        out[2 * BNN + gid] = g_u[gid];
        out[2 * BNN + (size_t)BB * NN + gid] = g_v[gid];
    }
}

extern "C" void kernel_launch(void* const* d_in, const int* in_sizes, int n_in,
                              void* d_out, int out_size) {
    const float* c = (const float*)d_in[0];
    const int SMEM = TROWS * TPAD * 4;          // 65,664 bytes

    cudaFuncSetAttribute(fat_pass_kernel,
                         cudaFuncAttributeMaxDynamicSharedMemorySize, SMEM);

    init_kernel<<<(BB * NN + 255) / 256, 256>>>();
    for (int it = 0; it < 50; ++it) {
        fat_pass_kernel<<<BB * NPART, 256, SMEM>>>(c);   // u + column partials
        vreduce_kernel<<<BB * NN / 32, 256>>>();         // partials -> v
    }
    final_kernel<<<BB * NN, 128>>>(c, (float*)d_out);
}

// round 15
// speedup vs baseline: 1.4705x; 1.0912x over previous
#include <cuda_runtime.h>
#include <cstdint>

// Sinkhorn: B=8, N=2048, eps=0.01, 50 fused (u,v) iterations.
//   u_i = eps*(log_mu - LSE_j((c_ij + v_j)/eps))   (old u cancels)
//   v_j = eps*(log_mu - LSE_i((c_ij + u_i)/eps))   (old v cancels)
// R15 = R14 + c streamed with ld.global.L2::evict_first.v4.b64 so the
//  once-read c stream does not evict the 32MB of column partials from L2;
//  partials then live entirely in L2 between fat pass and vreduce
//  (DRAM/iter ~198MB -> ~134MB). Lane owns 8 consecutive floats per load.
//  Phase A: chunk-local maxes, e' = 2^(x-m_h+64) -> smem, row (m, s') -> u;
//  per-(row,chunk) scale = 2^(m_h-m)*2^64/s'. Phase B: prod=e'*scale,
//  column max P, S = sum prod/P, partial=(lg2 P, S). vreduce:
//  v_new = v_old + C1*(64 - (M + lg2 S)).
// All __device__ scratch referenced from device code only.
// Outputs: [pi (B*N*N), -c (B*N*N), u (B*N), v (B*N)]

#define NN 2048
#define BB 8
#define TROWS 8                         // tile rows per CTA
#define NPART 256                       // row-groups (= NN/TROWS) per batch
#define TPAD 2052                       // padded tile row stride (floats)
#define SINK_S  144.26950408889634f     // 1/(eps*ln2) = 100*log2(e)
#define SINK_C0 -0.07624618986159398f   // eps*log_mu = -0.01*ln(2048)
#define SINK_C1 0.006931471805599453f   // eps*ln2

__device__ float g_u[BB * NN];
__device__ float g_v[BB * NN];
// Column-LSE partials, layout [p][b][j]: pm = lg2(tile col max), ps = scaled sum.
__device__ float g_pm[(size_t)NPART * BB * NN];
__device__ float g_ps[(size_t)NPART * BB * NN];

__device__ __forceinline__ float ex2f(float x) {
    float r; asm("ex2.approx.f32 %0, %1;" : "=f"(r) : "f"(x)); return r;
}
__device__ __forceinline__ float lg2f(float x) {
    float r; asm("lg2.approx.f32 %0, %1;" : "=f"(r) : "f"(x)); return r;
}
__device__ __forceinline__ float rcpf(float x) {
    float r; asm("rcp.approx.f32 %0, %1;" : "=f"(r) : "f"(x)); return r;
}
// 32-byte load (8 floats) with L2 evict-first priority (pure streaming data).
__device__ __forceinline__ void ldg8_ef(const float* p, float* o) {
    unsigned long long r0, r1, r2, r3;
    asm volatile("ld.global.L2::evict_first.v4.b64 {%0,%1,%2,%3}, [%4];"
                 : "=l"(r0), "=l"(r1), "=l"(r2), "=l"(r3) : "l"(p));
    o[0] = __uint_as_float((unsigned)r0); o[1] = __uint_as_float((unsigned)(r0 >> 32));
    o[2] = __uint_as_float((unsigned)r1); o[3] = __uint_as_float((unsigned)(r1 >> 32));
    o[4] = __uint_as_float((unsigned)r2); o[5] = __uint_as_float((unsigned)(r2 >> 32));
    o[6] = __uint_as_float((unsigned)r3); o[7] = __uint_as_float((unsigned)(r3 >> 32));
}

__global__ void __launch_bounds__(256) init_kernel() {
    int i = blockIdx.x * 256 + threadIdx.x;
    if (i < BB * NN) g_v[i] = 0.0f;
}

// ---- fat pass: grid = BB*NPART = 2048 CTAs, 256 threads (8 warps) ----
__global__ void __launch_bounds__(256, 3) fat_pass_kernel(const float* __restrict__ c) {
    extern __shared__ float tile[];              // [TROWS][TPAD] of e' values
    __shared__ float su_r[TROWS][2];             // per-(row,chunk) Phase-B scale
    const int b  = blockIdx.x >> 8;              // / NPART
    const int p  = blockIdx.x & (NPART - 1);
    const int r0 = p * TROWS;
    const int warp = threadIdx.x >> 5, lane = threadIdx.x & 31;
    const int row = r0 + warp;

    const float* __restrict__ crow = c + ((size_t)b * NN + row) * NN;
    const float* __restrict__ vvec = g_v + b * NN;

    // ---- Phase A: chunked row LSE with chunk-local maxes ----
    // Lane owns columns [h*1024 + k*256 + lane*8, +8) for k = 0..3.
    float mh[2], sh[2];
    #pragma unroll
    for (int h = 0; h < 2; h++) {
        float x[32];
        #pragma unroll
        for (int k = 0; k < 4; k++)
            ldg8_ef(crow + h * 1024 + k * 256 + lane * 8, x + k * 8);

        float m0 = -1e30f, m1 = -1e30f, m2 = -1e30f, m3 = -1e30f;
        #pragma unroll
        for (int k = 0; k < 4; k++) {
            const float4* wp = reinterpret_cast<const float4*>(
                vvec + h * 1024 + k * 256 + lane * 8);
            float4 wa = wp[0], wb = wp[1];
            float* xc = x + k * 8;
            xc[0] = (xc[0] + wa.x) * SINK_S;
            xc[1] = (xc[1] + wa.y) * SINK_S;
            xc[2] = (xc[2] + wa.z) * SINK_S;
            xc[3] = (xc[3] + wa.w) * SINK_S;
            xc[4] = (xc[4] + wb.x) * SINK_S;
            xc[5] = (xc[5] + wb.y) * SINK_S;
            xc[6] = (xc[6] + wb.z) * SINK_S;
            xc[7] = (xc[7] + wb.w) * SINK_S;
            m0 = fmaxf(m0, fmaxf(xc[0], xc[4]));
            m1 = fmaxf(m1, fmaxf(xc[1], xc[5]));
            m2 = fmaxf(m2, fmaxf(xc[2], xc[6]));
            m3 = fmaxf(m3, fmaxf(xc[3], xc[7]));
        }
        float m = fmaxf(fmaxf(m0, m1), fmaxf(m2, m3));
        #pragma unroll
        for (int off = 16; off; off >>= 1)
            m = fmaxf(m, __shfl_xor_sync(0xffffffffu, m, off));

        const float mb = m - 64.0f;                    // chunk bias
        float s0 = 0.f, s1 = 0.f, s2 = 0.f, s3 = 0.f;
        #pragma unroll
        for (int k = 0; k < 4; k++) {
            float* xc = x + k * 8;
            float4 ea, eb;
            ea.x = ex2f(xc[0] - mb);
            ea.y = ex2f(xc[1] - mb);
            ea.z = ex2f(xc[2] - mb);
            ea.w = ex2f(xc[3] - mb);
            eb.x = ex2f(xc[4] - mb);
            eb.y = ex2f(xc[5] - mb);
            eb.z = ex2f(xc[6] - mb);
            eb.w = ex2f(xc[7] - mb);
            s0 += ea.x + eb.x;
            s1 += ea.y + eb.y;
            s2 += ea.z + eb.z;
            s3 += ea.w + eb.w;
            float4* tp = reinterpret_cast<float4*>(
                &tile[warp * TPAD + h * 1024 + k * 256 + lane * 8]);
            tp[0] = ea;
            tp[1] = eb;
        }
        float s = (s0 + s1) + (s2 + s3);
        #pragma unroll
        for (int off = 16; off; off >>= 1)
            s += __shfl_xor_sync(0xffffffffu, s, off);
        mh[h] = m;
        sh[h] = s;
    }

    if (lane == 0) {
        // Combine chunks: s' = s0*2^(m0-m) + s1*2^(m1-m)  (2^64-biased units)
        float m = fmaxf(mh[0], mh[1]);
        float e0 = ex2f(mh[0] - m), e1 = ex2f(mh[1] - m);
        float s = fmaf(sh[0], e0, sh[1] * e1);
        // u = C0 - C1*(m + lg2 s_true), lg2 s_true = lg2 s - 64
        g_u[b * NN + row] = fmaf(-SINK_C1, m + lg2f(s) - 64.0f, SINK_C0);
        float rr = rcpf(s * 0x1p-64f);             // 2^64 / s'
        su_r[warp][0] = rr * e0;                   // scale for chunk 0
        su_r[warp][1] = rr * e1;                   // scale for chunk 1
    }
    __syncthreads();

    // ---- Phase B: column partials over the TROWS tile rows (no exps) ----
    #pragma unroll
    for (int g2 = 0; g2 < 2; g2++) {
        const int j0 = (threadIdx.x + (g2 << 8)) << 2;   // 4 cols, chunk = g2
        float4 prod[TROWS];
        float4 pm = make_float4(1e-18f, 1e-18f, 1e-18f, 1e-18f);
        #pragma unroll
        for (int r = 0; r < TROWS; r++) {
            float4 e = *reinterpret_cast<const float4*>(&tile[r * TPAD + j0]);
            float rr = su_r[r][g2];
            prod[r].x = e.x * rr;
            prod[r].y = e.y * rr;
            prod[r].z = e.z * rr;
            prod[r].w = e.w * rr;
            pm.x = fmaxf(pm.x, prod[r].x);
            pm.y = fmaxf(pm.y, prod[r].y);
            pm.z = fmaxf(pm.z, prod[r].z);
            pm.w = fmaxf(pm.w, prod[r].w);
        }
        float4 rp;
        rp.x = rcpf(pm.x); rp.y = rcpf(pm.y); rp.z = rcpf(pm.z); rp.w = rcpf(pm.w);
        float4 S4 = make_float4(0.f, 0.f, 0.f, 0.f);
        #pragma unroll
        for (int r = 0; r < TROWS; r++) {
            S4.x = fmaf(prod[r].x, rp.x, S4.x);
            S4.y = fmaf(prod[r].y, rp.y, S4.y);
            S4.z = fmaf(prod[r].z, rp.z, S4.z);
            S4.w = fmaf(prod[r].w, rp.w, S4.w);
        }
        float4 M4;
        M4.x = lg2f(pm.x); M4.y = lg2f(pm.y); M4.z = lg2f(pm.z); M4.w = lg2f(pm.w);

        const size_t pidx = ((size_t)(p * BB + b)) * NN + j0;
        *reinterpret_cast<float4*>(g_pm + pidx) = M4;
        *reinterpret_cast<float4*>(g_ps + pidx) = S4;
    }
}

// ---- v-reduce: merge NPART partials per column -> v ----
// Grid = BB*NN/32 = 512 CTAs; 8 warps; warp pg handles p in [pg*32, pg*32+32)
// for 32 consecutive columns (lane = column). Coalesced 128B lines, L2 hits.
__global__ void __launch_bounds__(256) vreduce_kernel() {
    __shared__ float sm_m[8][32], sm_s[8][32];
    const int tx = threadIdx.x & 31, pg = threadIdx.x >> 5;
    const int G = blockIdx.x * 32 + tx;            // global column id
    const int b = G >> 11, j = G & (NN - 1);

    float m[4] = {-1e30f, -1e30f, -1e30f, -1e30f};
    float s[4] = {0.f, 0.f, 0.f, 0.f};
    #pragma unroll
    for (int t = 0; t < 8; t++) {
        #pragma unroll
        for (int q = 0; q < 4; q++) {
            const int p = pg * 32 + q * 8 + t;
            const size_t idx = ((size_t)(p * BB + b)) * NN + j;
            float mp = g_pm[idx], sp = g_ps[idx];
            float mm = fmaxf(m[q], mp);
            s[q] = fmaf(s[q], ex2f(m[q] - mm), sp * ex2f(mp - mm));
            m[q] = mm;
        }
    }
    float M = fmaxf(fmaxf(m[0], m[1]), fmaxf(m[2], m[3]));
    float S = s[0] * ex2f(m[0] - M) + s[1] * ex2f(m[1] - M)
            + s[2] * ex2f(m[2] - M) + s[3] * ex2f(m[3] - M);
    sm_m[pg][tx] = M;
    sm_s[pg][tx] = S;
    __syncthreads();

    if (threadIdx.x < 32) {
        float Mf = sm_m[0][tx], Sf = sm_s[0][tx];
        #pragma unroll
        for (int k = 1; k < 8; k++) {
            float mp = sm_m[k][tx], sp = sm_s[k][tx];
            float mm = fmaxf(Mf, mp);
            Sf = fmaf(Sf, ex2f(Mf - mm), sp * ex2f(mp - mm));
            Mf = mm;
        }
        // v_new = v_old + C1 * (K - (M + lg2 S)), K = 64 (single net bias)
        const int gcol = blockIdx.x * 32 + tx;
        float v = g_v[gcol] + SINK_C1 * (64.0f - (Mf + lg2f(Sf)));
        if (v > 9e8f) v = 0.0f;                    // reference clamp
        g_v[gcol] = v;
    }
}

// ---- epilogue: pi = exp2((c+u+v)*S), -c, u, v ----
__global__ void __launch_bounds__(128) final_kernel(const float* __restrict__ c,
                                                    float* __restrict__ out) {
    const size_t BNN = (size_t)BB * NN * NN;
    const int rowid = blockIdx.x;
    const int b = rowid >> 11;
    const float u = g_u[rowid];
    const float4* __restrict__ crow =
        reinterpret_cast<const float4*>(c + (size_t)rowid * NN);
    const float4* __restrict__ vrow =
        reinterpret_cast<const float4*>(g_v + (size_t)b * NN);
    float4* pio = reinterpret_cast<float4*>(out + (size_t)rowid * NN);
    float4* nco = reinterpret_cast<float4*>(out + BNN + (size_t)rowid * NN);

    #pragma unroll 2
    for (int t = threadIdx.x; t < NN / 4; t += 128) {
        float4 cc = crow[t];
        float4 vv = vrow[t];
        float4 pi, nc;
        pi.x = ex2f(((cc.x + u) + vv.x) * SINK_S);
        pi.y = ex2f(((cc.y + u) + vv.y) * SINK_S);
        pi.z = ex2f(((cc.z + u) + vv.z) * SINK_S);
        pi.w = ex2f(((cc.w + u) + vv.w) * SINK_S);
        nc.x = -cc.x; nc.y = -cc.y; nc.z = -cc.z; nc.w = -cc.w;
        pio[t] = pi;
        nco[t] = nc;
    }
    int gid = blockIdx.x * 128 + threadIdx.x;
    if (gid < BB * NN) {
        out[2 * BNN + gid] = g_u[gid];
        out[2 * BNN + (size_t)BB * NN + gid] = g_v[gid];
    }
}

extern "C" void kernel_launch(void* const* d_in, const int* in_sizes, int n_in,
                              void* d_out, int out_size) {
    const float* c = (const float*)d_in[0];
    const int SMEM = TROWS * TPAD * 4;          // 65,664 bytes

    cudaFuncSetAttribute(fat_pass_kernel,
                         cudaFuncAttributeMaxDynamicSharedMemorySize, SMEM);

    init_kernel<<<(BB * NN + 255) / 256, 256>>>();
    for (int it = 0; it < 50; ++it) {
        fat_pass_kernel<<<BB * NPART, 256, SMEM>>>(c);   // u + column partials
        vreduce_kernel<<<BB * NN / 32, 256>>>();         // partials -> v
    }
    final_kernel<<<BB * NN, 128>>>(c, (float*)d_out);
}

// round 16
// speedup vs baseline: 1.6041x; 1.0909x over previous
#include <cuda_runtime.h>
#include <cstdint>

// Sinkhorn: B=8, N=2048, eps=0.01, 50 fused (u,v) iterations.
//   u_i = eps*(log_mu - LSE_j((c_ij + v_j)/eps))   (old u cancels)
//   v_j = eps*(log_mu - LSE_i((c_ij + u_i)/eps))   (old v cancels)
// R16: Phase-B partials are RAW SUMS (prod <= 2^64, tile sum <= 2^67: fp32
//  safe; underflowed tiles give harmless 0). g_pm deleted; Phase B = one
//  LDS+FMA sweep; vreduce = add tree + lg2; Phase A uses x = fma(c,S,w)
//  with w = v*S precomputed by vreduce. c streamed with evict_first so
//  partials + u/v stay L2-resident.
//  prod = 2^(y - C0*S + 64) => v_new = v_old + C1*(64 - lg2 Sum).
// All __device__ scratch referenced from device code only.
// Outputs: [pi (B*N*N), -c (B*N*N), u (B*N), v (B*N)]

#define NN 2048
#define BB 8
#define TROWS 8                         // tile rows per CTA
#define NPART 256                       // row-groups (= NN/TROWS) per batch
#define TPAD 2048                       // tile row stride (floats)
#define SINK_S  144.26950408889634f     // 1/(eps*ln2) = 100*log2(e)
#define SINK_C0 -0.07624618986159398f   // eps*log_mu = -0.01*ln(2048)
#define SINK_C1 0.006931471805599453f   // eps*ln2

__device__ float g_u[BB * NN];
__device__ float g_v[BB * NN];
__device__ float g_w[BB * NN];          // w = v * S (Phase-A operand)
// Column partial sums, layout [p][b][j] (raw 2^64-scaled sums).
__device__ float g_ps[(size_t)NPART * BB * NN];

__device__ __forceinline__ float ex2f(float x) {
    float r; asm("ex2.approx.f32 %0, %1;" : "=f"(r) : "f"(x)); return r;
}
__device__ __forceinline__ float lg2f(float x) {
    float r; asm("lg2.approx.f32 %0, %1;" : "=f"(r) : "f"(x)); return r;
}
__device__ __forceinline__ float rcpf(float x) {
    float r; asm("rcp.approx.f32 %0, %1;" : "=f"(r) : "f"(x)); return r;
}
// 32-byte load (8 floats) with L2 evict-first priority (pure streaming data).
__device__ __forceinline__ void ldg8_ef(const float* p, float* o) {
    unsigned long long r0, r1, r2, r3;
    asm volatile("ld.global.L2::evict_first.v4.b64 {%0,%1,%2,%3}, [%4];"
                 : "=l"(r0), "=l"(r1), "=l"(r2), "=l"(r3) : "l"(p));
    o[0] = __uint_as_float((unsigned)r0); o[1] = __uint_as_float((unsigned)(r0 >> 32));
    o[2] = __uint_as_float((unsigned)r1); o[3] = __uint_as_float((unsigned)(r1 >> 32));
    o[4] = __uint_as_float((unsigned)r2); o[5] = __uint_as_float((unsigned)(r2 >> 32));
    o[6] = __uint_as_float((unsigned)r3); o[7] = __uint_as_float((unsigned)(r3 >> 32));
}

__global__ void __launch_bounds__(256) init_kernel() {
    int i = blockIdx.x * 256 + threadIdx.x;
    if (i < BB * NN) { g_v[i] = 0.0f; g_w[i] = 0.0f; }
}

// ---- fat pass: grid = BB*NPART = 2048 CTAs, 256 threads (8 warps) ----
__global__ void __launch_bounds__(256, 3) fat_pass_kernel(const float* __restrict__ c) {
    extern __shared__ float tile[];              // [TROWS][TPAD] of e' values
    __shared__ float su_r[TROWS][2];             // per-(row,chunk) Phase-B scale
    const int b  = blockIdx.x >> 8;              // / NPART
    const int p  = blockIdx.x & (NPART - 1);
    const int r0 = p * TROWS;
    const int warp = threadIdx.x >> 5, lane = threadIdx.x & 31;
    const int row = r0 + warp;

    const float* __restrict__ crow = c + ((size_t)b * NN + row) * NN;
    const float* __restrict__ wvec = g_w + b * NN;

    // ---- Phase A: chunked row LSE with chunk-local maxes ----
    float mh[2], sh[2];
    #pragma unroll
    for (int h = 0; h < 2; h++) {
        float x[32];
        #pragma unroll
        for (int k = 0; k < 4; k++)
            ldg8_ef(crow + h * 1024 + k * 256 + lane * 8, x + k * 8);

        float m0 = -1e30f, m1 = -1e30f, m2 = -1e30f, m3 = -1e30f;
        #pragma unroll
        for (int k = 0; k < 4; k++) {
            const float4* wp = reinterpret_cast<const float4*>(
                wvec + h * 1024 + k * 256 + lane * 8);
            float4 wa = wp[0], wb = wp[1];
            float* xc = x + k * 8;
            xc[0] = fmaf(xc[0], SINK_S, wa.x);
            xc[1] = fmaf(xc[1], SINK_S, wa.y);
            xc[2] = fmaf(xc[2], SINK_S, wa.z);
            xc[3] = fmaf(xc[3], SINK_S, wa.w);
            xc[4] = fmaf(xc[4], SINK_S, wb.x);
            xc[5] = fmaf(xc[5], SINK_S, wb.y);
            xc[6] = fmaf(xc[6], SINK_S, wb.z);
            xc[7] = fmaf(xc[7], SINK_S, wb.w);
            m0 = fmaxf(m0, fmaxf(xc[0], xc[4]));
            m1 = fmaxf(m1, fmaxf(xc[1], xc[5]));
            m2 = fmaxf(m2, fmaxf(xc[2], xc[6]));
            m3 = fmaxf(m3, fmaxf(xc[3], xc[7]));
        }
        float m = fmaxf(fmaxf(m0, m1), fmaxf(m2, m3));
        #pragma unroll
        for (int off = 16; off; off >>= 1)
            m = fmaxf(m, __shfl_xor_sync(0xffffffffu, m, off));

        const float mb = m - 64.0f;                    // chunk bias
        float s0 = 0.f, s1 = 0.f, s2 = 0.f, s3 = 0.f;
        #pragma unroll
        for (int k = 0; k < 4; k++) {
            float* xc = x + k * 8;
            float4 ea, eb;
            ea.x = ex2f(xc[0] - mb);
            ea.y = ex2f(xc[1] - mb);
            ea.z = ex2f(xc[2] - mb);
            ea.w = ex2f(xc[3] - mb);
            eb.x = ex2f(xc[4] - mb);
            eb.y = ex2f(xc[5] - mb);
            eb.z = ex2f(xc[6] - mb);
            eb.w = ex2f(xc[7] - mb);
            s0 += ea.x + eb.x;
            s1 += ea.y + eb.y;
            s2 += ea.z + eb.z;
            s3 += ea.w + eb.w;
            float4* tp = reinterpret_cast<float4*>(
                &tile[warp * TPAD + h * 1024 + k * 256 + lane * 8]);
            tp[0] = ea;
            tp[1] = eb;
        }
        float s = (s0 + s1) + (s2 + s3);
        #pragma unroll
        for (int off = 16; off; off >>= 1)
            s += __shfl_xor_sync(0xffffffffu, s, off);
        mh[h] = m;
        sh[h] = s;
    }

    if (lane == 0) {
        // Combine chunks: s' = s0*2^(m0-m) + s1*2^(m1-m)  (2^64-biased units)
        float m = fmaxf(mh[0], mh[1]);
        float e0 = ex2f(mh[0] - m), e1 = ex2f(mh[1] - m);
        float s = fmaf(sh[0], e0, sh[1] * e1);
        // u = C0 - C1*(m + lg2 s_true), lg2 s_true = lg2 s - 64
        g_u[b * NN + row] = fmaf(-SINK_C1, m + lg2f(s) - 64.0f, SINK_C0);
        float rr = rcpf(s * 0x1p-64f);             // 1 / s_true
        su_r[warp][0] = rr * e0;                   // scale for chunk 0
        su_r[warp][1] = rr * e1;                   // scale for chunk 1
    }
    __syncthreads();

    // ---- Phase B: raw column sums over the TROWS tile rows (one sweep) ----
    #pragma unroll
    for (int g2 = 0; g2 < 2; g2++) {
        const int j0 = (threadIdx.x + (g2 << 8)) << 2;   // 4 cols, chunk = g2
        float4 S4 = make_float4(0.f, 0.f, 0.f, 0.f);
        #pragma unroll
        for (int r = 0; r < TROWS; r++) {
            float4 e = *reinterpret_cast<const float4*>(&tile[r * TPAD + j0]);
            float rr = su_r[r][g2];
            S4.x = fmaf(e.x, rr, S4.x);
            S4.y = fmaf(e.y, rr, S4.y);
            S4.z = fmaf(e.z, rr, S4.z);
            S4.w = fmaf(e.w, rr, S4.w);
        }
        const size_t pidx = ((size_t)(p * BB + b)) * NN + j0;
        *reinterpret_cast<float4*>(g_ps + pidx) = S4;
    }
}

// ---- v-reduce: sum NPART raw partials per column -> v (and w = v*S) ----
// Grid = BB*NN/32 = 512 CTAs; 8 warps; warp pg sums p in [pg*32, pg*32+32)
// for 32 consecutive columns (lane = column). Coalesced 128B lines, L2 hits.
__global__ void __launch_bounds__(256) vreduce_kernel() {
    __shared__ float sm[8][32];
    const int tx = threadIdx.x & 31, pg = threadIdx.x >> 5;
    const int G = blockIdx.x * 32 + tx;            // global column id
    const int b = G >> 11, j = G & (NN - 1);

    float s0 = 0.f, s1 = 0.f, s2 = 0.f, s3 = 0.f;
    #pragma unroll
    for (int t = 0; t < 8; t++) {
        const size_t base = (size_t)(pg * 32 + t) ;
        s0 += g_ps[((base +  0) * BB + b) * NN + j];
        s1 += g_ps[((base +  8) * BB + b) * NN + j];
        s2 += g_ps[((base + 16) * BB + b) * NN + j];
        s3 += g_ps[((base + 24) * BB + b) * NN + j];
    }
    sm[pg][tx] = (s0 + s1) + (s2 + s3);
    __syncthreads();

    if (threadIdx.x < 32) {
        float S = sm[0][tx];
        #pragma unroll
        for (int k = 1; k < 8; k++) S += sm[k][tx];
        // v_new = v_old + C1 * (64 - lg2 S)   (single net 2^64 bias)
        const int gcol = blockIdx.x * 32 + tx;
        float v = g_v[gcol] + SINK_C1 * (64.0f - lg2f(S));
        if (v > 9e8f) v = 0.0f;                    // reference clamp
        g_v[gcol] = v;
        g_w[gcol] = v * SINK_S;
    }
}

// ---- epilogue: pi = exp2((c+u+v)*S), -c, u, v ----
__global__ void __launch_bounds__(128) final_kernel(const float* __restrict__ c,
                                                    float* __restrict__ out) {
    const size_t BNN = (size_t)BB * NN * NN;
    const int rowid = blockIdx.x;
    const int b = rowid >> 11;
    const float u = g_u[rowid];
    const float4* __restrict__ crow =
        reinterpret_cast<const float4*>(c + (size_t)rowid * NN);
    const float4* __restrict__ vrow =
        reinterpret_cast<const float4*>(g_v + (size_t)b * NN);
    float4* pio = reinterpret_cast<float4*>(out + (size_t)rowid * NN);
    float4* nco = reinterpret_cast<float4*>(out + BNN + (size_t)rowid * NN);

    #pragma unroll 2
    for (int t = threadIdx.x; t < NN / 4; t += 128) {
        float4 cc = crow[t];
        float4 vv = vrow[t];
        float4 pi, nc;
        pi.x = ex2f(((cc.x + u) + vv.x) * SINK_S);
        pi.y = ex2f(((cc.y + u) + vv.y) * SINK_S);
        pi.z = ex2f(((cc.z + u) + vv.z) * SINK_S);
        pi.w = ex2f(((cc.w + u) + vv.w) * SINK_S);
        nc.x = -cc.x; nc.y = -cc.y; nc.z = -cc.z; nc.w = -cc.w;
        pio[t] = pi;
        nco[t] = nc;
    }
    int gid = blockIdx.x * 128 + threadIdx.x;
    if (gid < BB * NN) {
        out[2 * BNN + gid] = g_u[gid];
        out[2 * BNN + (size_t)BB * NN + gid] = g_v[gid];
    }
}

extern "C" void kernel_launch(void* const* d_in, const int* in_sizes, int n_in,
                              void* d_out, int out_size) {
    const float* c = (const float*)d_in[0];
    const int SMEM = TROWS * TPAD * 4;          // 65,536 bytes

    cudaFuncSetAttribute(fat_pass_kernel,
                         cudaFuncAttributeMaxDynamicSharedMemorySize, SMEM);

    init_kernel<<<(BB * NN + 255) / 256, 256>>>();
    for (int it = 0; it < 50; ++it) {
        fat_pass_kernel<<<BB * NPART, 256, SMEM>>>(c);   // u + column partials
        vreduce_kernel<<<BB * NN / 32, 256>>>();         // partials -> v, w
    }
    final_kernel<<<BB * NN, 128>>>(c, (float*)d_out);
}

// round 17
// speedup vs baseline: 1.7690x; 1.1028x over previous
#include <cuda_runtime.h>
#include <cstdint>

// Sinkhorn: B=8, N=2048, eps=0.01, 50 fused (u,v) iterations.
//   u_i = eps*(log_mu - LSE_j((c_ij + v_j)/eps))   (old u cancels)
//   v_j = eps*(log_mu - LSE_i((c_ij + u_i)/eps))   (old v cancels)
// R17 = R16 + e' staged in SMEM as bf16 (tile 64KB -> 32KB): L1 traffic
//  (the binding pipe at 65% in R16) drops ~32%, and launch_bounds(256,4)
//  gives 4 CTAs/SM. bf16 has full f32 exponent range (e' spans 2^-inf..2^64)
//  and its 0.1% per-element noise averages to ~2e-5 on column sums.
//  Unpack on read = shift/and (bf16 == top half of f32). Everything else
//  from R16: raw-sum partials, evict_first c stream, w = v*S operand,
//  v_new = v_old + C1*(64 - lg2 Sum).
// All __device__ scratch referenced from device code only.
// Outputs: [pi (B*N*N), -c (B*N*N), u (B*N), v (B*N)]

#define NN 2048
#define BB 8
#define TROWS 8                         // tile rows per CTA
#define NPART 256                       // row-groups (= NN/TROWS) per batch
#define SINK_S  144.26950408889634f     // 1/(eps*ln2) = 100*log2(e)
#define SINK_C0 -0.07624618986159398f   // eps*log_mu = -0.01*ln(2048)
#define SINK_C1 0.006931471805599453f   // eps*ln2

__device__ float g_u[BB * NN];
__device__ float g_v[BB * NN];
__device__ float g_w[BB * NN];          // w = v * S (Phase-A operand)
// Column partial sums, layout [p][b][j] (raw 2^64-scaled sums).
__device__ float g_ps[(size_t)NPART * BB * NN];

__device__ __forceinline__ float ex2f(float x) {
    float r; asm("ex2.approx.f32 %0, %1;" : "=f"(r) : "f"(x)); return r;
}
__device__ __forceinline__ float lg2f(float x) {
    float r; asm("lg2.approx.f32 %0, %1;" : "=f"(r) : "f"(x)); return r;
}
__device__ __forceinline__ float rcpf(float x) {
    float r; asm("rcp.approx.f32 %0, %1;" : "=f"(r) : "f"(x)); return r;
}
// Pack two f32 into bf16x2: lower half = lo, upper half = hi.
__device__ __forceinline__ uint32_t pack_bf16x2(float lo, float hi) {
    uint32_t r;
    asm("cvt.rn.bf16x2.f32 %0, %1, %2;" : "=r"(r) : "f"(hi), "f"(lo));
    return r;
}
// 32-byte load (8 floats) with L2 evict-first priority (pure streaming data).
__device__ __forceinline__ void ldg8_ef(const float* p, float* o) {
    unsigned long long r0, r1, r2, r3;
    asm volatile("ld.global.L2::evict_first.v4.b64 {%0,%1,%2,%3}, [%4];"
                 : "=l"(r0), "=l"(r1), "=l"(r2), "=l"(r3) : "l"(p));
    o[0] = __uint_as_float((unsigned)r0); o[1] = __uint_as_float((unsigned)(r0 >> 32));
    o[2] = __uint_as_float((unsigned)r1); o[3] = __uint_as_float((unsigned)(r1 >> 32));
    o[4] = __uint_as_float((unsigned)r2); o[5] = __uint_as_float((unsigned)(r2 >> 32));
    o[6] = __uint_as_float((unsigned)r3); o[7] = __uint_as_float((unsigned)(r3 >> 32));
}

__global__ void __launch_bounds__(256) init_kernel() {
    int i = blockIdx.x * 256 + threadIdx.x;
    if (i < BB * NN) { g_v[i] = 0.0f; g_w[i] = 0.0f; }
}

// ---- fat pass: grid = BB*NPART = 2048 CTAs, 256 threads (8 warps) ----
// smem: tile = TROWS rows x 1024 u32 (bf16x2) = 32KB.
__global__ void __launch_bounds__(256, 4) fat_pass_kernel(const float* __restrict__ c) {
    extern __shared__ uint32_t tileu[];          // [TROWS][1024] bf16x2 e'
    __shared__ float su_r[TROWS][2];             // per-(row,chunk) Phase-B scale
    const int b  = blockIdx.x >> 8;              // / NPART
    const int p  = blockIdx.x & (NPART - 1);
    const int r0 = p * TROWS;
    const int warp = threadIdx.x >> 5, lane = threadIdx.x & 31;
    const int row = r0 + warp;

    const float* __restrict__ crow = c + ((size_t)b * NN + row) * NN;
    const float* __restrict__ wvec = g_w + b * NN;

    // ---- Phase A: chunked row LSE with chunk-local maxes ----
    float mh[2], sh[2];
    #pragma unroll
    for (int h = 0; h < 2; h++) {
        float x[32];
        #pragma unroll
        for (int k = 0; k < 4; k++)
            ldg8_ef(crow + h * 1024 + k * 256 + lane * 8, x + k * 8);

        float m0 = -1e30f, m1 = -1e30f, m2 = -1e30f, m3 = -1e30f;
        #pragma unroll
        for (int k = 0; k < 4; k++) {
            const float4* wp = reinterpret_cast<const float4*>(
                wvec + h * 1024 + k * 256 + lane * 8);
            float4 wa = wp[0], wb = wp[1];
            float* xc = x + k * 8;
            xc[0] = fmaf(xc[0], SINK_S, wa.x);
            xc[1] = fmaf(xc[1], SINK_S, wa.y);
            xc[2] = fmaf(xc[2], SINK_S, wa.z);
            xc[3] = fmaf(xc[3], SINK_S, wa.w);
            xc[4] = fmaf(xc[4], SINK_S, wb.x);
            xc[5] = fmaf(xc[5], SINK_S, wb.y);
            xc[6] = fmaf(xc[6], SINK_S, wb.z);
            xc[7] = fmaf(xc[7], SINK_S, wb.w);
            m0 = fmaxf(m0, fmaxf(xc[0], xc[4]));
            m1 = fmaxf(m1, fmaxf(xc[1], xc[5]));
            m2 = fmaxf(m2, fmaxf(xc[2], xc[6]));
            m3 = fmaxf(m3, fmaxf(xc[3], xc[7]));
        }
        float m = fmaxf(fmaxf(m0, m1), fmaxf(m2, m3));
        #pragma unroll
        for (int off = 16; off; off >>= 1)
            m = fmaxf(m, __shfl_xor_sync(0xffffffffu, m, off));

        const float mb = m - 64.0f;                    // chunk bias
        float s0 = 0.f, s1 = 0.f, s2 = 0.f, s3 = 0.f;
        #pragma unroll
        for (int k = 0; k < 4; k++) {
            float* xc = x + k * 8;
            float e0 = ex2f(xc[0] - mb);
            float e1 = ex2f(xc[1] - mb);
            float e2 = ex2f(xc[2] - mb);
            float e3 = ex2f(xc[3] - mb);
            float e4 = ex2f(xc[4] - mb);
            float e5 = ex2f(xc[5] - mb);
            float e6 = ex2f(xc[6] - mb);
            float e7 = ex2f(xc[7] - mb);
            s0 += e0 + e4;
            s1 += e1 + e5;
            s2 += e2 + e6;
            s3 += e3 + e7;
            uint4 q;
            q.x = pack_bf16x2(e0, e1);
            q.y = pack_bf16x2(e2, e3);
            q.z = pack_bf16x2(e4, e5);
            q.w = pack_bf16x2(e6, e7);
            *reinterpret_cast<uint4*>(
                &tileu[warp * 1024 + h * 512 + k * 128 + lane * 4]) = q;
        }
        float s = (s0 + s1) + (s2 + s3);
        #pragma unroll
        for (int off = 16; off; off >>= 1)
            s += __shfl_xor_sync(0xffffffffu, s, off);
        mh[h] = m;
        sh[h] = s;
    }

    if (lane == 0) {
        // Combine chunks: s' = s0*2^(m0-m) + s1*2^(m1-m)  (2^64-biased units)
        float m = fmaxf(mh[0], mh[1]);
        float e0 = ex2f(mh[0] - m), e1 = ex2f(mh[1] - m);
        float s = fmaf(sh[0], e0, sh[1] * e1);
        // u = C0 - C1*(m + lg2 s_true), lg2 s_true = lg2 s - 64
        g_u[b * NN + row] = fmaf(-SINK_C1, m + lg2f(s) - 64.0f, SINK_C0);
        float rr = rcpf(s * 0x1p-64f);             // 1 / s_true
        su_r[warp][0] = rr * e0;                   // scale for chunk 0
        su_r[warp][1] = rr * e1;                   // scale for chunk 1
    }
    __syncthreads();

    // ---- Phase B: raw column sums, thread owns 8 columns (one sweep) ----
    {
        const int tx = threadIdx.x;
        const int hcol = tx >> 7;                  // chunk of these 8 columns
        float a0 = 0.f, a1 = 0.f, a2 = 0.f, a3 = 0.f;
        float a4 = 0.f, a5 = 0.f, a6 = 0.f, a7 = 0.f;
        #pragma unroll
        for (int r = 0; r < TROWS; r++) {
            uint4 q = *reinterpret_cast<const uint4*>(&tileu[r * 1024 + tx * 4]);
            float rr = su_r[r][hcol];
            a0 = fmaf(__uint_as_float(q.x << 16),          rr, a0);
            a1 = fmaf(__uint_as_float(q.x & 0xffff0000u),  rr, a1);
            a2 = fmaf(__uint_as_float(q.y << 16),          rr, a2);
            a3 = fmaf(__uint_as_float(q.y & 0xffff0000u),  rr, a3);
            a4 = fmaf(__uint_as_float(q.z << 16),          rr, a4);
            a5 = fmaf(__uint_as_float(q.z & 0xffff0000u),  rr, a5);
            a6 = fmaf(__uint_as_float(q.w << 16),          rr, a6);
            a7 = fmaf(__uint_as_float(q.w & 0xffff0000u),  rr, a7);
        }
        const size_t pidx = ((size_t)(p * BB + b)) * NN + tx * 8;
        *reinterpret_cast<float4*>(g_ps + pidx)     = make_float4(a0, a1, a2, a3);
        *reinterpret_cast<float4*>(g_ps + pidx + 4) = make_float4(a4, a5, a6, a7);
    }
}

// ---- v-reduce: sum NPART raw partials per column -> v (and w = v*S) ----
// Grid = BB*NN/32 = 512 CTAs; 8 warps; warp pg sums p in [pg*32, pg*32+32)
// for 32 consecutive columns (lane = column). Coalesced 128B lines, L2 hits.
__global__ void __launch_bounds__(256) vreduce_kernel() {
    __shared__ float sm[8][32];
    const int tx = threadIdx.x & 31, pg = threadIdx.x >> 5;
    const int G = blockIdx.x * 32 + tx;            // global column id
    const int b = G >> 11, j = G & (NN - 1);

    float s0 = 0.f, s1 = 0.f, s2 = 0.f, s3 = 0.f;
    #pragma unroll
    for (int t = 0; t < 8; t++) {
        const size_t base = (size_t)(pg * 32 + t);
        s0 += g_ps[((base +  0) * BB + b) * NN + j];
        s1 += g_ps[((base +  8) * BB + b) * NN + j];
        s2 += g_ps[((base + 16) * BB + b) * NN + j];
        s3 += g_ps[((base + 24) * BB + b) * NN + j];
    }
    sm[pg][tx] = (s0 + s1) + (s2 + s3);
    __syncthreads();

    if (threadIdx.x < 32) {
        float S = sm[0][tx];
        #pragma unroll
        for (int k = 1; k < 8; k++) S += sm[k][tx];
        // v_new = v_old + C1 * (64 - lg2 S)   (single net 2^64 bias)
        const int gcol = blockIdx.x * 32 + tx;
        float v = g_v[gcol] + SINK_C1 * (64.0f - lg2f(S));
        if (v > 9e8f) v = 0.0f;                    // reference clamp
        g_v[gcol] = v;
        g_w[gcol] = v * SINK_S;
    }
}

// ---- epilogue: pi = exp2((c+u+v)*S), -c, u, v ----
__global__ void __launch_bounds__(128) final_kernel(const float* __restrict__ c,
                                                    float* __restrict__ out) {
    const size_t BNN = (size_t)BB * NN * NN;
    const int rowid = blockIdx.x;
    const int b = rowid >> 11;
    const float u = g_u[rowid];
    const float4* __restrict__ crow =
        reinterpret_cast<const float4*>(c + (size_t)rowid * NN);
    const float4* __restrict__ vrow =
        reinterpret_cast<const float4*>(g_v + (size_t)b * NN);
    float4* pio = reinterpret_cast<float4*>(out + (size_t)rowid * NN);
    float4* nco = reinterpret_cast<float4*>(out + BNN + (size_t)rowid * NN);

    #pragma unroll 2
    for (int t = threadIdx.x; t < NN / 4; t += 128) {
        float4 cc = crow[t];
        float4 vv = vrow[t];
        float4 pi, nc;
        pi.x = ex2f(((cc.x + u) + vv.x) * SINK_S);
        pi.y = ex2f(((cc.y + u) + vv.y) * SINK_S);
        pi.z = ex2f(((cc.z + u) + vv.z) * SINK_S);
        pi.w = ex2f(((cc.w + u) + vv.w) * SINK_S);
        nc.x = -cc.x; nc.y = -cc.y; nc.z = -cc.z; nc.w = -cc.w;
        pio[t] = pi;
        nco[t] = nc;
    }
    int gid = blockIdx.x * 128 + threadIdx.x;
    if (gid < BB * NN) {
        out[2 * BNN + gid] = g_u[gid];
        out[2 * BNN + (size_t)BB * NN + gid] = g_v[gid];
    }
}

extern "C" void kernel_launch(void* const* d_in, const int* in_sizes, int n_in,
                              void* d_out, int out_size) {
    const float* c = (const float*)d_in[0];
    const int SMEM = TROWS * 1024 * 4;          // 32,768 bytes (bf16 tile)

    cudaFuncSetAttribute(fat_pass_kernel,
                         cudaFuncAttributeMaxDynamicSharedMemorySize, SMEM);

    init_kernel<<<(BB * NN + 255) / 256, 256>>>();
    for (int it = 0; it < 50; ++it) {
        fat_pass_kernel<<<BB * NPART, 256, SMEM>>>(c);   // u + column partials
        vreduce_kernel<<<BB * NN / 32, 256>>>();         // partials -> v, w
    }
    final_kernel<<<BB * NN, 128>>>(c, (float*)d_out);
}